// round 16
// baseline (speedup 1.0000x reference)
#include <cuda_runtime.h>
#include <cuda_bf16.h>
#include <cstdint>

#define NB 2
#define CD 256
#define NT 16384
#define INNER_C 1024
#define NHEAD 16

// RULE: never pass __device__ symbol addresses from host code (ATS silently reads host zeros).
// RULE: cp.async 16B needs 16B-aligned smem dst — all row strides must be multiples of 16.
__device__ float d_xn[NB*CD*NT];
__device__ float d_v[NB*INNER_C*NT];
__device__ __align__(256) __nv_bfloat16 d_qhi[NB*(long)INNER_C*NT];
__device__ __align__(256) __nv_bfloat16 d_qlo[NB*(long)INNER_C*NT];
__device__ __align__(256) __nv_bfloat16 d_khi[NB*(long)INNER_C*NT];
__device__ __align__(256) __nv_bfloat16 d_klo[NB*(long)INNER_C*NT];
__device__ float d_qpart[NB*INNER_C*32];
__device__ float d_kpart[NB*INNER_C*32];
__device__ float d_rnq[NB*INNER_C];
__device__ float d_rnk[NB*INNER_C];
__device__ float d_part[NB*NHEAD*8*64*64];
__device__ float d_attn[NB*NHEAD*64*64];
__device__ float d_p1[NB*CD*NT];
__device__ float d_pe[NB*CD*NT];
__device__ __align__(256) __nv_bfloat16 d_xhi[NB*(long)NT*INNER_C];
__device__ __align__(256) __nv_bfloat16 d_xlo[NB*(long)NT*INNER_C];
__device__ __align__(256) __nv_bfloat16 d_whi[CD*INNER_C];
__device__ __align__(256) __nv_bfloat16 d_wlo[CD*INNER_C];

// ================= helpers =================
__device__ __forceinline__ uint32_t smem_u32(const void* p){
  uint32_t a;
  asm("{ .reg .u64 t; cvta.to.shared.u64 t, %1; cvt.u32.u64 %0, t; }" : "=r"(a) : "l"(p));
  return a;
}
#define CP_ASYNC16(sa, ga) asm volatile("cp.async.cg.shared.global [%0], [%1], 16;" :: "r"((uint32_t)(sa)), "l"(ga) : "memory")
#define CP_COMMIT() asm volatile("cp.async.commit_group;" ::: "memory")
#define CP_WAITG(n) asm volatile("cp.async.wait_group %0;" :: "n"(n) : "memory")

__device__ __forceinline__ uint32_t lds32(uint32_t a){
  uint32_t v; asm volatile("ld.shared.b32 %0, [%1];" : "=r"(v) : "r"(a)); return v;
}
__device__ __forceinline__ void mma16816(float* c, const uint32_t* a, const uint32_t* b){
  asm volatile("mma.sync.aligned.m16n8k16.row.col.f32.bf16.bf16.f32 "
    "{%0,%1,%2,%3}, {%4,%5,%6,%7}, {%8,%9}, {%0,%1,%2,%3};"
    : "+f"(c[0]),"+f"(c[1]),"+f"(c[2]),"+f"(c[3])
    : "r"(a[0]),"r"(a[1]),"r"(a[2]),"r"(a[3]), "r"(b[0]),"r"(b[1]));
}
__device__ __forceinline__ void split_bf16(float x, __nv_bfloat16& h, __nv_bfloat16& l){
  h = __float2bfloat16(x);
  l = __float2bfloat16(x - __bfloat162float(h));
}

// ================= GEMM2: split-bf16, KCH=32, occupancy 2 (A = xo bf16) =================
#define ROWB 80
#define QOFF 10240
#define STAGE_BYTES 40960
#define GEMM_SMEM (2*STAGE_BYTES)

__global__ void __launch_bounds__(256,2) gemm_mma_kernel(
    const float* __restrict__ bias, float* __restrict__ out_arg)
{
  extern __shared__ char smem[];
  uint32_t sb = smem_u32(smem);
  int tid = threadIdx.x;
  int lane = tid & 31, wid = tid >> 5;
  int warpM = wid >> 2, warpN = wid & 3;
  int ny = blockIdx.x;
  int mtile = blockIdx.y;
  int b  = blockIdx.z;
  int m0 = mtile*128;

  const __nv_bfloat16* gq[4];
  gq[0] = d_xhi + ((long)b*NT + m0)*1024;
  gq[1] = d_xlo + ((long)b*NT + m0)*1024;
  gq[2] = d_whi + (long)ny*128*1024;
  gq[3] = d_wlo + (long)ny*128*1024;

  float acc[4][4][4];
  #pragma unroll
  for (int i=0;i<4;i++)
    #pragma unroll
    for (int j=0;j<4;j++)
      #pragma unroll
      for (int r=0;r<4;r++) acc[i][j][r]=0.f;

  auto issue = [&](int cc, int s){
    uint32_t st = sb + (uint32_t)s*STAGE_BYTES;
    int k0 = cc*32;
    #pragma unroll
    for (int p = 0; p < 8; p++){
      int idx = p*256 + tid;
      int q = idx >> 9;
      int local = idx & 511;
      int r = local >> 2, c16 = local & 3;
      CP_ASYNC16(st + (uint32_t)q*QOFF + (uint32_t)r*ROWB + (uint32_t)c16*16,
                 gq[q] + (long)r*1024 + k0 + c16*8);
    }
    CP_COMMIT();
  };

  issue(0, 0);

  int g4 = lane >> 2;
  int kb2 = (lane & 3)*2;

  for (int c = 0; c < 32; c++){
    int s = c & 1;
    if (c+1 < 32){ issue(c+1, 1-s); CP_WAITG(1); }
    else         { CP_WAITG(0); }
    __syncthreads();

    uint32_t st = sb + (uint32_t)s*STAGE_BYTES;
    #pragma unroll
    for (int j = 0; j < 2; j++){
      uint32_t koff = (uint32_t)(j*16 + kb2)*2;
      uint32_t Ahf[4][4], Alf[4][4];
      #pragma unroll
      for (int mt = 0; mt < 4; mt++){
        uint32_t r0 = (uint32_t)(warpM*64 + mt*16 + g4);
        uint32_t a0 = st + r0*ROWB + koff;
        Ahf[mt][0] = lds32(a0);
        Ahf[mt][1] = lds32(a0 + 8*ROWB);
        Ahf[mt][2] = lds32(a0 + 16);
        Ahf[mt][3] = lds32(a0 + 8*ROWB + 16);
        uint32_t a1 = a0 + QOFF;
        Alf[mt][0] = lds32(a1);
        Alf[mt][1] = lds32(a1 + 8*ROWB);
        Alf[mt][2] = lds32(a1 + 16);
        Alf[mt][3] = lds32(a1 + 8*ROWB + 16);
      }
      #pragma unroll
      for (int nt = 0; nt < 4; nt++){
        uint32_t nr = (uint32_t)(warpN*32 + nt*8 + g4);
        uint32_t b0a = st + 2u*QOFF + nr*ROWB + koff;
        uint32_t bh[2], bl[2];
        bh[0] = lds32(b0a);        bh[1] = lds32(b0a + 16);
        bl[0] = lds32(b0a + QOFF); bl[1] = lds32(b0a + QOFF + 16);
        #pragma unroll
        for (int mt = 0; mt < 4; mt++){
          mma16816(acc[mt][nt], Ahf[mt], bh);
          mma16816(acc[mt][nt], Alf[mt], bh);
          mma16816(acc[mt][nt], Ahf[mt], bl);
        }
      }
    }
    __syncthreads();
  }

  int mb0 = m0 + warpM*64;
  int nc0 = ny*128 + warpN*32;
  #pragma unroll
  for (int mt = 0; mt < 4; mt++){
    int r0 = mb0 + mt*16 + (lane >> 2);
    #pragma unroll
    for (int nt = 0; nt < 4; nt++){
      int ccn = nc0 + nt*8 + (lane & 3)*2;
      float b0 = __ldg(&bias[ccn]), b1 = __ldg(&bias[ccn+1]);
      long o0 = ((long)b*NT + r0)*256 + ccn;
      long o1 = o0 + 8L*256;
      float2 p0 = *(const float2*)&d_pe[o0];
      float2 p1 = *(const float2*)&d_pe[o1];
      float2 v0, v1;
      v0.x = acc[mt][nt][0] + b0 + p0.x; v0.y = acc[mt][nt][1] + b1 + p0.y;
      v1.x = acc[mt][nt][2] + b0 + p1.x; v1.y = acc[mt][nt][3] + b1 + p1.y;
      *(float2*)&out_arg[o0] = v0;
      *(float2*)&out_arg[o1] = v1;
    }
  }
}

// ================= GEMM1: A from fp32 d_v with in-kernel transpose+split =================
// 16B-aligned row strides everywhere (VS 528, A/B 80).
#define GV_ROWB 80
#define GV_QOFF 10240           // 128*80
#define GV_VS 0
#define GV_AH 16896             // VS = 32 rows * 528B
#define GV_AL 27136
#define GV_BH 37376
#define GV_BL 47616
#define GV_STAGE 57856
#define GEMMV_SMEM (2*GV_STAGE) // 115712

__global__ void __launch_bounds__(256) gemm_v_kernel(const float* __restrict__ bias)
{
  extern __shared__ char smem[];
  uint32_t sb = smem_u32(smem);
  int tid = threadIdx.x;
  int lane = tid & 31, wid = tid >> 5;
  int warpM = wid >> 2, warpN = wid & 3;
  int ny = blockIdx.x;
  int mtile = blockIdx.y;
  int b  = blockIdx.z;
  int m0 = mtile*128;

  const float* Vg = d_v + (long)b*INNER_C*NT;
  const __nv_bfloat16* Wh = d_whi + (long)ny*128*1024;
  const __nv_bfloat16* Wl = d_wlo + (long)ny*128*1024;

  float acc[4][4][4];
  #pragma unroll
  for (int i=0;i<4;i++)
    #pragma unroll
    for (int j=0;j<4;j++)
      #pragma unroll
      for (int r=0;r<4;r++) acc[i][j][r]=0.f;

  auto issue = [&](int cc, int s){
    uint32_t st = sb + (uint32_t)s*GV_STAGE;
    int k0 = cc*32;
    // fp32 V tile: 32 rows(k) x 128 tokens, 528B padded rows -> 1024 16B units
    #pragma unroll
    for (int p = 0; p < 4; p++){
      int idx = p*256 + tid;
      int kr = idx >> 5, u = idx & 31;
      CP_ASYNC16(st + GV_VS + (uint32_t)kr*528 + (uint32_t)u*16,
                 Vg + (long)(k0+kr)*NT + m0 + u*4);
    }
    // W hi/lo: 2 arrays x 128 rows x 4 units (80B rows)
    #pragma unroll
    for (int p = 0; p < 4; p++){
      int idx = p*256 + tid;
      int arr = idx >> 9;
      int local = idx & 511;
      int r = local >> 2, u = local & 3;
      const __nv_bfloat16* g = arr ? Wl : Wh;
      CP_ASYNC16(st + (arr ? GV_BL : GV_BH) + (uint32_t)r*GV_ROWB + (uint32_t)u*16,
                 g + (long)r*1024 + k0 + u*8);
    }
    CP_COMMIT();
  };

  issue(0, 0);

  int g4 = lane >> 2;
  int kb2 = (lane & 3)*2;
  int kp = tid >> 4, tg = tid & 15;   // convert mapping: kpair 0..15, token group

  for (int c = 0; c < 32; c++){
    int s = c & 1;
    if (c+1 < 32){ issue(c+1, 1-s); CP_WAITG(1); }
    else         { CP_WAITG(0); }
    __syncthreads();

    // convert fp32 VS -> split-bf16 A layout [token][k]
    {
      char* st = smem + (size_t)s*GV_STAGE;
      const float* v0p = (const float*)(st + GV_VS + (2*kp)*528);
      const float* v1p = (const float*)(st + GV_VS + (2*kp+1)*528);
      #pragma unroll
      for (int i = 0; i < 8; i++){
        int t = tg + 16*i;
        float x0 = v0p[t], x1 = v1p[t];
        __nv_bfloat16 h0,l0,h1,l1;
        split_bf16(x0,h0,l0); split_bf16(x1,h1,l1);
        *(__nv_bfloat162*)(st + GV_AH + t*GV_ROWB + kp*4) = __nv_bfloat162(h0,h1);
        *(__nv_bfloat162*)(st + GV_AL + t*GV_ROWB + kp*4) = __nv_bfloat162(l0,l1);
      }
    }
    __syncthreads();

    uint32_t stb = sb + (uint32_t)s*GV_STAGE;
    #pragma unroll
    for (int j = 0; j < 2; j++){
      uint32_t koff = (uint32_t)(j*16 + kb2)*2;
      uint32_t Ahf[4][4], Alf[4][4];
      #pragma unroll
      for (int mt = 0; mt < 4; mt++){
        uint32_t r0 = (uint32_t)(warpM*64 + mt*16 + g4);
        uint32_t a0 = stb + GV_AH + r0*GV_ROWB + koff;
        Ahf[mt][0] = lds32(a0);
        Ahf[mt][1] = lds32(a0 + 8*GV_ROWB);
        Ahf[mt][2] = lds32(a0 + 16);
        Ahf[mt][3] = lds32(a0 + 8*GV_ROWB + 16);
        uint32_t a1 = a0 + (GV_AL - GV_AH);
        Alf[mt][0] = lds32(a1);
        Alf[mt][1] = lds32(a1 + 8*GV_ROWB);
        Alf[mt][2] = lds32(a1 + 16);
        Alf[mt][3] = lds32(a1 + 8*GV_ROWB + 16);
      }
      #pragma unroll
      for (int nt = 0; nt < 4; nt++){
        uint32_t nr = (uint32_t)(warpN*32 + nt*8 + g4);
        uint32_t b0a = stb + GV_BH + nr*GV_ROWB + koff;
        uint32_t bh[2], bl[2];
        bh[0] = lds32(b0a);                     bh[1] = lds32(b0a + 16);
        bl[0] = lds32(b0a + (GV_BL - GV_BH));   bl[1] = lds32(b0a + (GV_BL - GV_BH) + 16);
        #pragma unroll
        for (int mt = 0; mt < 4; mt++){
          mma16816(acc[mt][nt], Ahf[mt], bh);
          mma16816(acc[mt][nt], Alf[mt], bh);
          mma16816(acc[mt][nt], Ahf[mt], bl);
        }
      }
    }
    __syncthreads();
  }

  int mb0 = m0 + warpM*64;
  int nc0 = ny*128 + warpN*32;
  #pragma unroll
  for (int mt = 0; mt < 4; mt++){
    int r0 = mb0 + mt*16 + (lane >> 2);
    #pragma unroll
    for (int nt = 0; nt < 4; nt++){
      int ccn = nc0 + nt*8 + (lane & 3)*2;
      float b0 = __ldg(&bias[ccn]), b1 = __ldg(&bias[ccn+1]);
      long o0 = ((long)b*NT + r0)*256 + ccn;
      long o1 = o0 + 8L*256;
      float2 v0, v1;
      v0.x = acc[mt][nt][0] + b0; v0.y = acc[mt][nt][1] + b1;
      v1.x = acc[mt][nt][2] + b0; v1.y = acc[mt][nt][3] + b1;
      *(float2*)&d_p1[o0] = v0;
      *(float2*)&d_p1[o1] = v1;
    }
  }
}

// ================= attn logits: 8 chunks of 2048 tokens =================
#define AROWB 144
#define AQOFF (64*AROWB)
#define ASTAGE (4*AQOFF)
#define ATTN_SMEM (2*ASTAGE)

__global__ void __launch_bounds__(128,2) attn_mma_kernel(){
  extern __shared__ char smem[];
  uint32_t sb = smem_u32(smem);
  int tid = threadIdx.x, lane = tid & 31, wid = tid >> 5;
  int ch = blockIdx.x, h = blockIdx.y, b = blockIdx.z;
  long cb = ((long)b*INNER_C + h*64)*NT;
  const __nv_bfloat16* gq[4] = { d_khi + cb, d_klo + cb, d_qhi + cb, d_qlo + cb };
  int n0 = ch*2048;

  float acc[8][4];
  #pragma unroll
  for (int i=0;i<8;i++)
    #pragma unroll
    for (int r=0;r<4;r++) acc[i][r]=0.f;

  auto issue = [&](int cc, int s){
    uint32_t st = sb + (uint32_t)s*ASTAGE;
    int nb = n0 + cc*64;
    #pragma unroll
    for (int p = 0; p < 16; p++){
      int idx = p*128 + tid;
      int q = idx >> 9;
      int local = idx & 511;
      int r = local >> 3, c16 = local & 7;
      CP_ASYNC16(st + (uint32_t)q*AQOFF + (uint32_t)r*AROWB + (uint32_t)c16*16,
                 gq[q] + (long)r*NT + nb + c16*8);
    }
    CP_COMMIT();
  };

  issue(0, 0);
  int g4 = lane >> 2, kb2 = (lane & 3)*2;

  for (int c = 0; c < 32; c++){
    int s = c & 1;
    if (c+1 < 32){ issue(c+1, 1-s); CP_WAITG(1); }
    else         { CP_WAITG(0); }
    __syncthreads();

    uint32_t st = sb + (uint32_t)s*ASTAGE;
    #pragma unroll
    for (int j = 0; j < 4; j++){
      uint32_t koff = (uint32_t)(j*16 + kb2)*2;
      uint32_t a0 = st + (uint32_t)(wid*16 + g4)*AROWB + koff;
      uint32_t Ah[4], Al[4];
      Ah[0] = lds32(a0);          Ah[1] = lds32(a0 + 8*AROWB);
      Ah[2] = lds32(a0 + 16);     Ah[3] = lds32(a0 + 8*AROWB + 16);
      uint32_t a1 = a0 + AQOFF;
      Al[0] = lds32(a1);          Al[1] = lds32(a1 + 8*AROWB);
      Al[2] = lds32(a1 + 16);     Al[3] = lds32(a1 + 8*AROWB + 16);
      #pragma unroll
      for (int nt = 0; nt < 8; nt++){
        uint32_t b0a = st + 2u*AQOFF + (uint32_t)(nt*8 + g4)*AROWB + koff;
        uint32_t bh[2], bl[2];
        bh[0] = lds32(b0a);         bh[1] = lds32(b0a + 16);
        bl[0] = lds32(b0a + AQOFF); bl[1] = lds32(b0a + AQOFF + 16);
        mma16816(acc[nt], Ah, bh);
        mma16816(acc[nt], Al, bh);
        mma16816(acc[nt], Ah, bl);
      }
    }
    __syncthreads();
  }

  float* pp = d_part + ((long)((b*NHEAD + h)*8 + ch))*4096;
  int r0 = wid*16 + g4;
  #pragma unroll
  for (int nt = 0; nt < 8; nt++){
    int col = nt*8 + (lane & 3)*2;
    float2 w0; w0.x = acc[nt][0]; w0.y = acc[nt][1];
    float2 w1; w1.x = acc[nt][2]; w1.y = acc[nt][3];
    *(float2*)&pp[r0*64 + col] = w0;
    *(float2*)&pp[(r0+8)*64 + col] = w1;
  }
}

// ================= xo = attn @ v, B staged from fp32 d_v =================
#define XROWB 144
#define XA_SZ (64*XROWB)
#define XB_SZ (128*XROWB)
#define X_VS (2*XA_SZ + 2*XB_SZ)       // 55296
#define XO_SMEM (X_VS + 64*528)        // + 33792 = 89088

__global__ void __launch_bounds__(128,2) xo_mma_kernel(){
  extern __shared__ char smem[];
  uint32_t sb = smem_u32(smem);
  uint32_t sAh = sb, sAl = sb + XA_SZ, sBh = sb + 2*XA_SZ, sBl = sBh + XB_SZ;
  int tid = threadIdx.x, lane = tid & 31, wid = tid >> 5;
  int ntile = blockIdx.x, h = blockIdx.y, b = blockIdx.z;
  int t0 = ntile*128;

  // stage fp32 v tile [64 e][128 t] (528B padded rows)
  {
    #pragma unroll
    for (int p = 0; p < 16; p++){
      int idx = p*128 + tid;
      int er = idx >> 5, u = idx & 31;
      CP_ASYNC16(sb + X_VS + (uint32_t)er*528 + (uint32_t)u*16,
                 d_v + ((long)b*INNER_C + h*64 + er)*NT + t0 + u*4);
    }
    CP_COMMIT();
  }
  // A: attn 64x64 fp32 -> split bf16 smem
  {
    const float* ap = d_attn + (long)(b*NHEAD+h)*4096;
    for (int i = tid; i < 4096; i += 128){
      float x = ap[i];
      __nv_bfloat16 hh, ll;
      split_bf16(x, hh, ll);
      int d = i >> 6, e = i & 63;
      *(__nv_bfloat16*)(smem + d*XROWB + e*2) = hh;
      *(__nv_bfloat16*)(smem + XA_SZ + d*XROWB + e*2) = ll;
    }
  }
  CP_WAITG(0);
  __syncthreads();

  // convert fp32 VS [e][t] -> split bf16 B [t][e]
  {
    int ep = tid >> 2, tg = tid & 3;
    const float* v0p = (const float*)(smem + X_VS + (2*ep)*528);
    const float* v1p = (const float*)(smem + X_VS + (2*ep+1)*528);
    #pragma unroll
    for (int i = 0; i < 32; i++){
      int t = tg + 4*i;
      float x0 = v0p[t], x1 = v1p[t];
      __nv_bfloat16 h0,l0,h1,l1;
      split_bf16(x0,h0,l0); split_bf16(x1,h1,l1);
      *(__nv_bfloat162*)(smem + 2*XA_SZ + t*XROWB + ep*4) = __nv_bfloat162(h0,h1);
      *(__nv_bfloat162*)(smem + 2*XA_SZ + XB_SZ + t*XROWB + ep*4) = __nv_bfloat162(l0,l1);
    }
  }
  __syncthreads();

  int g4 = lane >> 2, kb2 = (lane & 3)*2;
  float acc[4][4][4];
  #pragma unroll
  for (int i=0;i<4;i++)
    #pragma unroll
    for (int j=0;j<4;j++)
      #pragma unroll
      for (int r=0;r<4;r++) acc[i][j][r]=0.f;

  #pragma unroll
  for (int j = 0; j < 4; j++){
    uint32_t koff = (uint32_t)(j*16 + kb2)*2;
    uint32_t Ahf[4][4], Alf[4][4];
    #pragma unroll
    for (int mt = 0; mt < 4; mt++){
      uint32_t a0 = sAh + (uint32_t)(mt*16 + g4)*XROWB + koff;
      Ahf[mt][0] = lds32(a0);
      Ahf[mt][1] = lds32(a0 + 8*XROWB);
      Ahf[mt][2] = lds32(a0 + 16);
      Ahf[mt][3] = lds32(a0 + 8*XROWB + 16);
      uint32_t a1 = a0 + XA_SZ;
      Alf[mt][0] = lds32(a1);
      Alf[mt][1] = lds32(a1 + 8*XROWB);
      Alf[mt][2] = lds32(a1 + 16);
      Alf[mt][3] = lds32(a1 + 8*XROWB + 16);
    }
    #pragma unroll
    for (int nt = 0; nt < 4; nt++){
      uint32_t nr = (uint32_t)(wid*32 + nt*8 + g4);
      uint32_t b0a = sBh + nr*XROWB + koff;
      uint32_t bh[2], bl[2];
      bh[0] = lds32(b0a);         bh[1] = lds32(b0a + 16);
      bl[0] = lds32(b0a + XB_SZ); bl[1] = lds32(b0a + XB_SZ + 16);
      #pragma unroll
      for (int mt = 0; mt < 4; mt++){
        mma16816(acc[mt][nt], Ahf[mt], bh);
        mma16816(acc[mt][nt], Alf[mt], bh);
        mma16816(acc[mt][nt], Ahf[mt], bl);
      }
    }
  }

  #pragma unroll
  for (int mt = 0; mt < 4; mt++){
    int d0 = mt*16 + g4;
    #pragma unroll
    for (int nt = 0; nt < 4; nt++){
      int tt = t0 + wid*32 + nt*8 + kb2;
      long o0 = ((long)b*INNER_C + h*64 + d0)*NT + tt;
      long o1 = o0 + 8L*NT;
      __nv_bfloat16 h0,l0,h1,l1;
      split_bf16(acc[mt][nt][0], h0, l0);
      split_bf16(acc[mt][nt][1], h1, l1);
      *(__nv_bfloat162*)&d_xhi[o0] = __nv_bfloat162(h0,h1);
      *(__nv_bfloat162*)&d_xlo[o0] = __nv_bfloat162(l0,l1);
      split_bf16(acc[mt][nt][2], h0, l0);
      split_bf16(acc[mt][nt][3], h1, l1);
      *(__nv_bfloat162*)&d_xhi[o1] = __nv_bfloat162(h0,h1);
      *(__nv_bfloat162*)&d_xlo[o1] = __nv_bfloat162(l0,l1);
    }
  }
}

// ================= conversions / transposes =================
__global__ void convert_w_kernel(const float* __restrict__ W){
  int i = blockIdx.x*256 + threadIdx.x;
  __nv_bfloat16 h, l;
  split_bf16(W[i], h, l);
  d_whi[i] = h; d_wlo[i] = l;
}

__global__ void transpose_x_kernel(const float* __restrict__ x_in){
  __shared__ float tile[32][33];
  int b = blockIdx.z;
  int n0 = blockIdx.x*32, c0 = blockIdx.y*32;
  int tx = threadIdx.x, ty = threadIdx.y;
  tile[ty][tx] = x_in[((long)b*NT + n0+ty)*CD + c0+tx];
  __syncthreads();
  d_xn[((long)b*CD + c0+ty)*NT + n0+tx] = tile[tx][ty];
}

// ---------------- fused dwconv + BN: one CTA per ci plane, all 4 ocs, 2 tokens/thread ----------------
__global__ void __launch_bounds__(256) conv_qkv_kernel(
    const float* __restrict__ wq, const float* __restrict__ wk, const float* __restrict__ wv,
    const float* __restrict__ gq, const float* __restrict__ bq, const float* __restrict__ mq, const float* __restrict__ vq,
    const float* __restrict__ gk, const float* __restrict__ bk, const float* __restrict__ mk, const float* __restrict__ vk,
    const float* __restrict__ gv, const float* __restrict__ bv, const float* __restrict__ mv, const float* __restrict__ vv)
{
  int b = blockIdx.z, ci = blockIdx.y;
  int tid = threadIdx.x, lane = tid & 31, wrp = tid >> 5;
  int bx = blockIdx.x;
  int nn = (bx*256 + tid)*2;
  int hh = nn >> 7, ww = nn & 127;
  const float* xp = d_xn + ((long)b*CD + ci)*NT;

  float xv[3][4];
  #pragma unroll
  for (int dy=0; dy<3; dy++){
    int y = hh+dy-1;
    #pragma unroll
    for (int t=0; t<4; t++){
      int x = ww-1+t;
      xv[dy][t] = ((unsigned)y < 128u && (unsigned)x < 128u) ? xp[y*128+x] : 0.f;
    }
  }

  float part[8];
  #pragma unroll
  for (int j = 0; j < 4; j++){
    int oc = ci*4 + j;
    float wr0[9], wr1[9], wr2[9];
    #pragma unroll
    for (int i=0;i<9;i++){ wr0[i]=__ldg(&wq[oc*9+i]); wr1[i]=__ldg(&wk[oc*9+i]); wr2[i]=__ldg(&wv[oc*9+i]); }
    float sq0=0,sq1=0,sk0=0,sk1=0,sv0=0,sv1=0;
    #pragma unroll
    for (int dy=0; dy<3; dy++)
      #pragma unroll
      for (int t=0; t<3; t++){
        float w0=wr0[dy*3+t], w1=wr1[dy*3+t], w2=wr2[dy*3+t];
        sq0 = fmaf(xv[dy][t],   w0, sq0); sq1 = fmaf(xv[dy][t+1], w0, sq1);
        sk0 = fmaf(xv[dy][t],   w1, sk0); sk1 = fmaf(xv[dy][t+1], w1, sk1);
        sv0 = fmaf(xv[dy][t],   w2, sv0); sv1 = fmaf(xv[dy][t+1], w2, sv1);
      }
    float aq = __ldg(&gq[oc])*rsqrtf(__ldg(&vq[oc])+1e-5f), mqo = __ldg(&mq[oc]), bqo = __ldg(&bq[oc]);
    float ak = __ldg(&gk[oc])*rsqrtf(__ldg(&vk[oc])+1e-5f), mko = __ldg(&mk[oc]), bko = __ldg(&bk[oc]);
    float av = __ldg(&gv[oc])*rsqrtf(__ldg(&vv[oc])+1e-5f), mvo = __ldg(&mv[oc]), bvo = __ldg(&bv[oc]);
    float yq0 = (sq0-mqo)*aq + bqo, yq1 = (sq1-mqo)*aq + bqo;
    float yk0 = (sk0-mko)*ak + bko, yk1 = (sk1-mko)*ak + bko;
    float yv0 = (sv0-mvo)*av + bvo, yv1 = (sv1-mvo)*av + bvo;
    long o = ((long)b*INNER_C + oc)*NT + nn;
    __nv_bfloat16 h0,l0,h1,l1;
    split_bf16(yq0,h0,l0); split_bf16(yq1,h1,l1);
    *(__nv_bfloat162*)&d_qhi[o] = __nv_bfloat162(h0,h1);
    *(__nv_bfloat162*)&d_qlo[o] = __nv_bfloat162(l0,l1);
    split_bf16(yk0,h0,l0); split_bf16(yk1,h1,l1);
    *(__nv_bfloat162*)&d_khi[o] = __nv_bfloat162(h0,h1);
    *(__nv_bfloat162*)&d_klo[o] = __nv_bfloat162(l0,l1);
    float2 vv2; vv2.x = yv0; vv2.y = yv1;
    *(float2*)&d_v[o] = vv2;
    part[j]   = yq0*yq0 + yq1*yq1;
    part[4+j] = yk0*yk0 + yk1*yk1;
  }

  #pragma unroll
  for (int v = 0; v < 8; v++)
    #pragma unroll
    for (int off = 16; off > 0; off >>= 1)
      part[v] += __shfl_down_sync(0xffffffffu, part[v], off);

  __shared__ float s_red[8][8];
  if (lane == 0){
    #pragma unroll
    for (int v = 0; v < 8; v++) s_red[wrp][v] = part[v];
  }
  __syncthreads();
  if (tid < 64){
    int w = tid & 7, v = tid >> 3;
    float x = s_red[w][v];
    x += __shfl_down_sync(0xffffffffu, x, 4, 8);
    x += __shfl_down_sync(0xffffffffu, x, 2, 8);
    x += __shfl_down_sync(0xffffffffu, x, 1, 8);
    if (w == 0){
      int j = v & 3;
      long oc = (long)ci*4 + j;
      if (v < 4) d_qpart[((long)b*INNER_C + oc)*32 + bx] = x;
      else       d_kpart[((long)b*INNER_C + oc)*32 + bx] = x;
    }
  }
}

__global__ void norms_kernel(){
  int idx = blockIdx.x*256 + threadIdx.x;
  float sq=0.f, sk=0.f;
  #pragma unroll 8
  for (int c=0;c<32;c++){ sq += d_qpart[(long)idx*32+c]; sk += d_kpart[(long)idx*32+c]; }
  d_rnq[idx] = 1.f/fmaxf(sqrtf(sq),1e-12f);
  d_rnk[idx] = 1.f/fmaxf(sqrtf(sk),1e-12f);
}

__global__ void softmax_kernel(const float* __restrict__ rescale){
  int h = blockIdx.x, b = blockIdx.y;
  int d = threadIdx.x;
  float acc[64];
  #pragma unroll
  for (int e=0;e<64;e++) acc[e]=0.f;
  const float* base = d_part + ((long)(b*NHEAD+h)*8)*4096 + d*64;
  for (int ch=0; ch<8; ch++){
    const float* p = base + (long)ch*4096;
    #pragma unroll
    for (int e=0;e<64;e++) acc[e] += p[e];
  }
  float sc = rescale[h]*d_rnk[b*INNER_C + h*64 + d];
  const float* rq = &d_rnq[b*INNER_C + h*64];
  float m = -1e30f;
  #pragma unroll
  for (int e=0;e<64;e++){ acc[e] = acc[e]*sc*rq[e]; m = fmaxf(m, acc[e]); }
  float s = 0.f;
  #pragma unroll
  for (int e=0;e<64;e++){ acc[e] = expf(acc[e]-m); s += acc[e]; }
  float inv = 1.f/s;
  float* ap = d_attn + ((long)(b*NHEAD+h)*64 + d)*64;
  #pragma unroll
  for (int e=0;e<64;e++) ap[e] = acc[e]*inv;
}

// ---------------- FUSED positional convs: 16x16 token tile x 64 channels ----------------
#define P_VP_SZ (20*20*64)
#define P_G_SZ  (18*18*64)
#define POS_SMEM ((P_VP_SZ + P_G_SZ)*4)

__global__ void __launch_bounds__(256,1) conv_pos_fused_kernel(
    const float* __restrict__ w1, const float* __restrict__ w2)
{
  extern __shared__ float sm[];
  float* s_vp = sm;
  float* s_g  = sm + P_VP_SZ;
  int tid = threadIdx.x;
  int bx = blockIdx.x, c0 = blockIdx.y*64, b = blockIdx.z;
  int tx0 = (bx & 7)*16, ty0 = (bx >> 3)*16;

  #pragma unroll
  for (int i = 0; i < 25; i++){
    int idx = i*256 + tid;
    int tok = idx >> 4, c4 = (idx & 15)*4;
    int y = tok/20, x = tok - y*20;
    int gy = ty0 + y - 2, gx = tx0 + x - 2;
    float4 v = {0.f,0.f,0.f,0.f};
    if ((unsigned)gy < 128u && (unsigned)gx < 128u)
      v = *(const float4*)&d_p1[((long)b*NT + gy*128 + gx)*256 + c0 + c4];
    *(float4*)&s_vp[tok*64 + c4] = v;
  }
  __syncthreads();

  int qd = tid & 15, wk = tid >> 4;
  int cch = qd*4;
  {
    float wr[4][9];
    #pragma unroll
    for (int j=0;j<4;j++)
      #pragma unroll
      for (int i=0;i<9;i++) wr[j][i] = __ldg(&w1[(c0+cch+j)*9+i]);
    for (int t = wk; t < 324; t += 16){
      int y = t/18, x = t - y*18;
      int gy = ty0 + y - 1, gx = tx0 + x - 1;
      float4 o = {0.f,0.f,0.f,0.f};
      if ((unsigned)gy < 128u && (unsigned)gx < 128u){
        float a0=0,a1=0,a2=0,a3=0;
        #pragma unroll
        for (int dy=0; dy<3; dy++)
          #pragma unroll
          for (int dx=0; dx<3; dx++){
            float4 xv = *(const float4*)&s_vp[((y+dy)*20 + (x+dx))*64 + cch];
            int kk = dy*3+dx;
            a0 = fmaf(xv.x, wr[0][kk], a0);
            a1 = fmaf(xv.y, wr[1][kk], a1);
            a2 = fmaf(xv.z, wr[2][kk], a2);
            a3 = fmaf(xv.w, wr[3][kk], a3);
          }
        o.x = 0.5f*a0*(1.f+erff(a0*0.70710678118654752f));
        o.y = 0.5f*a1*(1.f+erff(a1*0.70710678118654752f));
        o.z = 0.5f*a2*(1.f+erff(a2*0.70710678118654752f));
        o.w = 0.5f*a3*(1.f+erff(a3*0.70710678118654752f));
      }
      *(float4*)&s_g[t*64 + cch] = o;
    }
  }
  __syncthreads();

  {
    float wr[4][9];
    #pragma unroll
    for (int j=0;j<4;j++)
      #pragma unroll
      for (int i=0;i<9;i++) wr[j][i] = __ldg(&w2[(c0+cch+j)*9+i]);
    for (int t = wk; t < 256; t += 16){
      int y = t >> 4, x = t & 15;
      float a0=0,a1=0,a2=0,a3=0;
      #pragma unroll
      for (int dy=0; dy<3; dy++)
        #pragma unroll
        for (int dx=0; dx<3; dx++){
          float4 xv = *(const float4*)&s_g[((y+dy)*18 + (x+dx))*64 + cch];
          int kk = dy*3+dx;
          a0 = fmaf(xv.x, wr[0][kk], a0);
          a1 = fmaf(xv.y, wr[1][kk], a1);
          a2 = fmaf(xv.z, wr[2][kk], a2);
          a3 = fmaf(xv.w, wr[3][kk], a3);
        }
      float4 o; o.x=a0; o.y=a1; o.z=a2; o.w=a3;
      *(float4*)&d_pe[((long)b*NT + (ty0+y)*128 + tx0+x)*256 + c0 + cch] = o;
    }
  }
}

extern "C" void kernel_launch(void* const* d_in, const int* in_sizes, int n_in,
                              void* d_out, int out_size) {
  const float* x_in  = (const float*)d_in[0];
  const float* wq    = (const float*)d_in[1];
  const float* wk    = (const float*)d_in[2];
  const float* wv    = (const float*)d_in[3];
  const float* bnq_g = (const float*)d_in[4];
  const float* bnq_b = (const float*)d_in[5];
  const float* bnq_m = (const float*)d_in[6];
  const float* bnq_v = (const float*)d_in[7];
  const float* bnk_g = (const float*)d_in[8];
  const float* bnk_b = (const float*)d_in[9];
  const float* bnk_m = (const float*)d_in[10];
  const float* bnk_v = (const float*)d_in[11];
  const float* bnv_g = (const float*)d_in[12];
  const float* bnv_b = (const float*)d_in[13];
  const float* bnv_m = (const float*)d_in[14];
  const float* bnv_v = (const float*)d_in[15];
  const float* rescale = (const float*)d_in[16];
  const float* proj_w  = (const float*)d_in[17];
  const float* proj_b  = (const float*)d_in[18];
  const float* pos_w1  = (const float*)d_in[19];
  const float* pos_w2  = (const float*)d_in[20];
  float* out = (float*)d_out;

  static int inited = 0;
  static cudaStream_t s1;
  static cudaEvent_t ev0, ev1;
  if (!inited){
    cudaFuncSetAttribute(gemm_mma_kernel, cudaFuncAttributeMaxDynamicSharedMemorySize, GEMM_SMEM);
    cudaFuncSetAttribute(gemm_v_kernel, cudaFuncAttributeMaxDynamicSharedMemorySize, GEMMV_SMEM);
    cudaFuncSetAttribute(attn_mma_kernel, cudaFuncAttributeMaxDynamicSharedMemorySize, ATTN_SMEM);
    cudaFuncSetAttribute(xo_mma_kernel, cudaFuncAttributeMaxDynamicSharedMemorySize, XO_SMEM);
    cudaFuncSetAttribute(conv_pos_fused_kernel, cudaFuncAttributeMaxDynamicSharedMemorySize, POS_SMEM);
    cudaStreamCreateWithFlags(&s1, cudaStreamNonBlocking);
    cudaEventCreateWithFlags(&ev0, cudaEventDisableTiming);
    cudaEventCreateWithFlags(&ev1, cudaEventDisableTiming);
    inited = 1;
  }

  transpose_x_kernel<<<dim3(NT/32, CD/32, NB), dim3(32,32)>>>(x_in);
  conv_qkv_kernel<<<dim3(NT/512, CD, NB), 256>>>(
      wq, wk, wv,
      bnq_g, bnq_b, bnq_m, bnq_v,
      bnk_g, bnk_b, bnk_m, bnk_v,
      bnv_g, bnv_b, bnv_m, bnv_v);
  cudaEventRecord(ev0, 0);

  // attention chain on s1 (xo needs only conv_qkv outputs + softmax)
  cudaStreamWaitEvent(s1, ev0, 0);
  norms_kernel<<<8, 256, 0, s1>>>();
  attn_mma_kernel<<<dim3(8, NHEAD, NB), 128, ATTN_SMEM, s1>>>();
  softmax_kernel<<<dim3(NHEAD, NB), 64, 0, s1>>>(rescale);
  xo_mma_kernel<<<dim3(NT/128, NHEAD, NB), 128, XO_SMEM, s1>>>();
  cudaEventRecord(ev1, s1);

  // projection chain on stream 0 (concurrent with s1)
  convert_w_kernel<<<(CD*INNER_C)/256, 256>>>(proj_w);
  gemm_v_kernel<<<dim3(2, 128, NB), 256, GEMMV_SMEM>>>(proj_b);
  conv_pos_fused_kernel<<<dim3(64, 4, NB), 256, POS_SMEM>>>(pos_w1, pos_w2);

  // final GEMM2 (needs xo [ev1] + pe [stream order])
  cudaStreamWaitEvent(0, ev1, 0);
  gemm_mma_kernel<<<dim3(2, 128, NB), 256, GEMM_SMEM>>>(proj_b, out);
}

// round 17
// speedup vs baseline: 1.0683x; 1.0683x over previous
#include <cuda_runtime.h>
#include <cuda_bf16.h>
#include <cstdint>

#define NB 2
#define CD 256
#define NT 16384
#define INNER_C 1024
#define NHEAD 16

// RULE: never pass __device__ symbol addresses from host code (ATS silently reads host zeros).
// RULE: cp.async 16B needs 16B-aligned smem dst — all row strides must be multiples of 16.
__device__ float d_xn[NB*CD*NT];
__device__ float d_v[NB*INNER_C*NT];
__device__ __align__(256) __nv_bfloat16 d_qhi[NB*(long)INNER_C*NT];
__device__ __align__(256) __nv_bfloat16 d_qlo[NB*(long)INNER_C*NT];
__device__ __align__(256) __nv_bfloat16 d_khi[NB*(long)INNER_C*NT];
__device__ __align__(256) __nv_bfloat16 d_klo[NB*(long)INNER_C*NT];
__device__ float d_qpart[NB*INNER_C*32];
__device__ float d_kpart[NB*INNER_C*32];
__device__ float d_rnq[NB*INNER_C];
__device__ float d_rnk[NB*INNER_C];
__device__ float d_part[NB*NHEAD*8*64*64];
__device__ float d_attn[NB*NHEAD*64*64];
__device__ float d_p1[NB*CD*NT];
__device__ float d_pe[NB*CD*NT];
__device__ __align__(256) __nv_bfloat16 d_xhi[NB*(long)NT*INNER_C];
__device__ __align__(256) __nv_bfloat16 d_xlo[NB*(long)NT*INNER_C];
__device__ __align__(256) __nv_bfloat16 d_whi[CD*INNER_C];
__device__ __align__(256) __nv_bfloat16 d_wlo[CD*INNER_C];

// ================= helpers =================
__device__ __forceinline__ uint32_t smem_u32(const void* p){
  uint32_t a;
  asm("{ .reg .u64 t; cvta.to.shared.u64 t, %1; cvt.u32.u64 %0, t; }" : "=r"(a) : "l"(p));
  return a;
}
#define CP_ASYNC16(sa, ga) asm volatile("cp.async.cg.shared.global [%0], [%1], 16;" :: "r"((uint32_t)(sa)), "l"(ga) : "memory")
#define CP_COMMIT() asm volatile("cp.async.commit_group;" ::: "memory")
#define CP_WAITG(n) asm volatile("cp.async.wait_group %0;" :: "n"(n) : "memory")

__device__ __forceinline__ uint32_t lds32(uint32_t a){
  uint32_t v; asm volatile("ld.shared.b32 %0, [%1];" : "=r"(v) : "r"(a)); return v;
}
__device__ __forceinline__ void mma16816(float* c, const uint32_t* a, const uint32_t* b){
  asm volatile("mma.sync.aligned.m16n8k16.row.col.f32.bf16.bf16.f32 "
    "{%0,%1,%2,%3}, {%4,%5,%6,%7}, {%8,%9}, {%0,%1,%2,%3};"
    : "+f"(c[0]),"+f"(c[1]),"+f"(c[2]),"+f"(c[3])
    : "r"(a[0]),"r"(a[1]),"r"(a[2]),"r"(a[3]), "r"(b[0]),"r"(b[1]));
}
__device__ __forceinline__ void split_bf16(float x, __nv_bfloat16& h, __nv_bfloat16& l){
  h = __float2bfloat16(x);
  l = __float2bfloat16(x - __bfloat162float(h));
}

// ================= GEMM2: split-bf16, KCH=32, occupancy 2 (A = xo bf16) =================
#define ROWB 80
#define QOFF 10240
#define STAGE_BYTES 40960
#define GEMM_SMEM (2*STAGE_BYTES)

__global__ void __launch_bounds__(256,2) gemm_mma_kernel(
    const float* __restrict__ bias, float* __restrict__ out_arg)
{
  extern __shared__ char smem[];
  uint32_t sb = smem_u32(smem);
  int tid = threadIdx.x;
  int lane = tid & 31, wid = tid >> 5;
  int warpM = wid >> 2, warpN = wid & 3;
  int ny = blockIdx.x;
  int mtile = blockIdx.y;
  int b  = blockIdx.z;
  int m0 = mtile*128;

  const __nv_bfloat16* gq[4];
  gq[0] = d_xhi + ((long)b*NT + m0)*1024;
  gq[1] = d_xlo + ((long)b*NT + m0)*1024;
  gq[2] = d_whi + (long)ny*128*1024;
  gq[3] = d_wlo + (long)ny*128*1024;

  float acc[4][4][4];
  #pragma unroll
  for (int i=0;i<4;i++)
    #pragma unroll
    for (int j=0;j<4;j++)
      #pragma unroll
      for (int r=0;r<4;r++) acc[i][j][r]=0.f;

  auto issue = [&](int cc, int s){
    uint32_t st = sb + (uint32_t)s*STAGE_BYTES;
    int k0 = cc*32;
    #pragma unroll
    for (int p = 0; p < 8; p++){
      int idx = p*256 + tid;
      int q = idx >> 9;
      int local = idx & 511;
      int r = local >> 2, c16 = local & 3;
      CP_ASYNC16(st + (uint32_t)q*QOFF + (uint32_t)r*ROWB + (uint32_t)c16*16,
                 gq[q] + (long)r*1024 + k0 + c16*8);
    }
    CP_COMMIT();
  };

  issue(0, 0);

  int g4 = lane >> 2;
  int kb2 = (lane & 3)*2;

  for (int c = 0; c < 32; c++){
    int s = c & 1;
    if (c+1 < 32){ issue(c+1, 1-s); CP_WAITG(1); }
    else         { CP_WAITG(0); }
    __syncthreads();

    uint32_t st = sb + (uint32_t)s*STAGE_BYTES;
    #pragma unroll
    for (int j = 0; j < 2; j++){
      uint32_t koff = (uint32_t)(j*16 + kb2)*2;
      uint32_t Ahf[4][4], Alf[4][4];
      #pragma unroll
      for (int mt = 0; mt < 4; mt++){
        uint32_t r0 = (uint32_t)(warpM*64 + mt*16 + g4);
        uint32_t a0 = st + r0*ROWB + koff;
        Ahf[mt][0] = lds32(a0);
        Ahf[mt][1] = lds32(a0 + 8*ROWB);
        Ahf[mt][2] = lds32(a0 + 16);
        Ahf[mt][3] = lds32(a0 + 8*ROWB + 16);
        uint32_t a1 = a0 + QOFF;
        Alf[mt][0] = lds32(a1);
        Alf[mt][1] = lds32(a1 + 8*ROWB);
        Alf[mt][2] = lds32(a1 + 16);
        Alf[mt][3] = lds32(a1 + 8*ROWB + 16);
      }
      #pragma unroll
      for (int nt = 0; nt < 4; nt++){
        uint32_t nr = (uint32_t)(warpN*32 + nt*8 + g4);
        uint32_t b0a = st + 2u*QOFF + nr*ROWB + koff;
        uint32_t bh[2], bl[2];
        bh[0] = lds32(b0a);        bh[1] = lds32(b0a + 16);
        bl[0] = lds32(b0a + QOFF); bl[1] = lds32(b0a + QOFF + 16);
        #pragma unroll
        for (int mt = 0; mt < 4; mt++){
          mma16816(acc[mt][nt], Ahf[mt], bh);
          mma16816(acc[mt][nt], Alf[mt], bh);
          mma16816(acc[mt][nt], Ahf[mt], bl);
        }
      }
    }
    __syncthreads();
  }

  int mb0 = m0 + warpM*64;
  int nc0 = ny*128 + warpN*32;
  #pragma unroll
  for (int mt = 0; mt < 4; mt++){
    int r0 = mb0 + mt*16 + (lane >> 2);
    #pragma unroll
    for (int nt = 0; nt < 4; nt++){
      int ccn = nc0 + nt*8 + (lane & 3)*2;
      float b0 = __ldg(&bias[ccn]), b1 = __ldg(&bias[ccn+1]);
      long o0 = ((long)b*NT + r0)*256 + ccn;
      long o1 = o0 + 8L*256;
      float2 p0 = *(const float2*)&d_pe[o0];
      float2 p1 = *(const float2*)&d_pe[o1];
      float2 v0, v1;
      v0.x = acc[mt][nt][0] + b0 + p0.x; v0.y = acc[mt][nt][1] + b1 + p0.y;
      v1.x = acc[mt][nt][2] + b0 + p1.x; v1.y = acc[mt][nt][3] + b1 + p1.y;
      *(float2*)&out_arg[o0] = v0;
      *(float2*)&out_arg[o1] = v1;
    }
  }
}

// ================= GEMM1: A from fp32 d_v with in-kernel transpose+split =================
// VS rows 512B (16B-aligned); stage 57344 -> 2 stages = 114688 -> occupancy 2.
#define GV_ROWB 80
#define GV_VS 0
#define GV_AH 16384             // VS = 32 rows * 512B
#define GV_AL 26624
#define GV_BH 36864
#define GV_BL 47104
#define GV_STAGE 57344
#define GEMMV_SMEM (2*GV_STAGE) // 114688

__global__ void __launch_bounds__(256,2) gemm_v_kernel(const float* __restrict__ bias)
{
  extern __shared__ char smem[];
  uint32_t sb = smem_u32(smem);
  int tid = threadIdx.x;
  int lane = tid & 31, wid = tid >> 5;
  int warpM = wid >> 2, warpN = wid & 3;
  int ny = blockIdx.x;
  int mtile = blockIdx.y;
  int b  = blockIdx.z;
  int m0 = mtile*128;

  const float* Vg = d_v + (long)b*INNER_C*NT;
  const __nv_bfloat16* Wh = d_whi + (long)ny*128*1024;
  const __nv_bfloat16* Wl = d_wlo + (long)ny*128*1024;

  float acc[4][4][4];
  #pragma unroll
  for (int i=0;i<4;i++)
    #pragma unroll
    for (int j=0;j<4;j++)
      #pragma unroll
      for (int r=0;r<4;r++) acc[i][j][r]=0.f;

  auto issue = [&](int cc, int s){
    uint32_t st = sb + (uint32_t)s*GV_STAGE;
    int k0 = cc*32;
    // fp32 V tile: 32 rows(k) x 128 tokens, 512B rows -> 1024 16B units
    #pragma unroll
    for (int p = 0; p < 4; p++){
      int idx = p*256 + tid;
      int kr = idx >> 5, u = idx & 31;
      CP_ASYNC16(st + GV_VS + (uint32_t)kr*512 + (uint32_t)u*16,
                 Vg + (long)(k0+kr)*NT + m0 + u*4);
    }
    // W hi/lo: 2 arrays x 128 rows x 4 units (80B rows)
    #pragma unroll
    for (int p = 0; p < 4; p++){
      int idx = p*256 + tid;
      int arr = idx >> 9;
      int local = idx & 511;
      int r = local >> 2, u = local & 3;
      const __nv_bfloat16* g = arr ? Wl : Wh;
      CP_ASYNC16(st + (arr ? GV_BL : GV_BH) + (uint32_t)r*GV_ROWB + (uint32_t)u*16,
                 g + (long)r*1024 + k0 + u*8);
    }
    CP_COMMIT();
  };

  issue(0, 0);

  int g4 = lane >> 2;
  int kb2 = (lane & 3)*2;
  int kp = tid >> 4, tg = tid & 15;   // convert mapping: kpair 0..15, token group

  for (int c = 0; c < 32; c++){
    int s = c & 1;
    if (c+1 < 32){ issue(c+1, 1-s); CP_WAITG(1); }
    else         { CP_WAITG(0); }
    __syncthreads();

    // convert fp32 VS -> split-bf16 A layout [token][k]
    {
      char* st = smem + (size_t)s*GV_STAGE;
      const float* v0p = (const float*)(st + GV_VS + (2*kp)*512);
      const float* v1p = (const float*)(st + GV_VS + (2*kp+1)*512);
      #pragma unroll
      for (int i = 0; i < 8; i++){
        int t = tg + 16*i;
        float x0 = v0p[t], x1 = v1p[t];
        __nv_bfloat16 h0,l0,h1,l1;
        split_bf16(x0,h0,l0); split_bf16(x1,h1,l1);
        *(__nv_bfloat162*)(st + GV_AH + t*GV_ROWB + kp*4) = __nv_bfloat162(h0,h1);
        *(__nv_bfloat162*)(st + GV_AL + t*GV_ROWB + kp*4) = __nv_bfloat162(l0,l1);
      }
    }
    __syncthreads();

    uint32_t stb = sb + (uint32_t)s*GV_STAGE;
    #pragma unroll
    for (int j = 0; j < 2; j++){
      uint32_t koff = (uint32_t)(j*16 + kb2)*2;
      uint32_t Ahf[4][4], Alf[4][4];
      #pragma unroll
      for (int mt = 0; mt < 4; mt++){
        uint32_t r0 = (uint32_t)(warpM*64 + mt*16 + g4);
        uint32_t a0 = stb + GV_AH + r0*GV_ROWB + koff;
        Ahf[mt][0] = lds32(a0);
        Ahf[mt][1] = lds32(a0 + 8*GV_ROWB);
        Ahf[mt][2] = lds32(a0 + 16);
        Ahf[mt][3] = lds32(a0 + 8*GV_ROWB + 16);
        uint32_t a1 = a0 + (GV_AL - GV_AH);
        Alf[mt][0] = lds32(a1);
        Alf[mt][1] = lds32(a1 + 8*GV_ROWB);
        Alf[mt][2] = lds32(a1 + 16);
        Alf[mt][3] = lds32(a1 + 8*GV_ROWB + 16);
      }
      #pragma unroll
      for (int nt = 0; nt < 4; nt++){
        uint32_t nr = (uint32_t)(warpN*32 + nt*8 + g4);
        uint32_t b0a = stb + GV_BH + nr*GV_ROWB + koff;
        uint32_t bh[2], bl[2];
        bh[0] = lds32(b0a);                     bh[1] = lds32(b0a + 16);
        bl[0] = lds32(b0a + (GV_BL - GV_BH));   bl[1] = lds32(b0a + (GV_BL - GV_BH) + 16);
        #pragma unroll
        for (int mt = 0; mt < 4; mt++){
          mma16816(acc[mt][nt], Ahf[mt], bh);
          mma16816(acc[mt][nt], Alf[mt], bh);
          mma16816(acc[mt][nt], Ahf[mt], bl);
        }
      }
    }
    __syncthreads();
  }

  int mb0 = m0 + warpM*64;
  int nc0 = ny*128 + warpN*32;
  #pragma unroll
  for (int mt = 0; mt < 4; mt++){
    int r0 = mb0 + mt*16 + (lane >> 2);
    #pragma unroll
    for (int nt = 0; nt < 4; nt++){
      int ccn = nc0 + nt*8 + (lane & 3)*2;
      float b0 = __ldg(&bias[ccn]), b1 = __ldg(&bias[ccn+1]);
      long o0 = ((long)b*NT + r0)*256 + ccn;
      long o1 = o0 + 8L*256;
      float2 v0, v1;
      v0.x = acc[mt][nt][0] + b0; v0.y = acc[mt][nt][1] + b1;
      v1.x = acc[mt][nt][2] + b0; v1.y = acc[mt][nt][3] + b1;
      *(float2*)&d_p1[o0] = v0;
      *(float2*)&d_p1[o1] = v1;
    }
  }
}

// ================= attn logits: 8 chunks of 2048 tokens =================
#define AROWB 144
#define AQOFF (64*AROWB)
#define ASTAGE (4*AQOFF)
#define ATTN_SMEM (2*ASTAGE)

__global__ void __launch_bounds__(128,2) attn_mma_kernel(){
  extern __shared__ char smem[];
  uint32_t sb = smem_u32(smem);
  int tid = threadIdx.x, lane = tid & 31, wid = tid >> 5;
  int ch = blockIdx.x, h = blockIdx.y, b = blockIdx.z;
  long cb = ((long)b*INNER_C + h*64)*NT;
  const __nv_bfloat16* gq[4] = { d_khi + cb, d_klo + cb, d_qhi + cb, d_qlo + cb };
  int n0 = ch*2048;

  float acc[8][4];
  #pragma unroll
  for (int i=0;i<8;i++)
    #pragma unroll
    for (int r=0;r<4;r++) acc[i][r]=0.f;

  auto issue = [&](int cc, int s){
    uint32_t st = sb + (uint32_t)s*ASTAGE;
    int nb = n0 + cc*64;
    #pragma unroll
    for (int p = 0; p < 16; p++){
      int idx = p*128 + tid;
      int q = idx >> 9;
      int local = idx & 511;
      int r = local >> 3, c16 = local & 7;
      CP_ASYNC16(st + (uint32_t)q*AQOFF + (uint32_t)r*AROWB + (uint32_t)c16*16,
                 gq[q] + (long)r*NT + nb + c16*8);
    }
    CP_COMMIT();
  };

  issue(0, 0);
  int g4 = lane >> 2, kb2 = (lane & 3)*2;

  for (int c = 0; c < 32; c++){
    int s = c & 1;
    if (c+1 < 32){ issue(c+1, 1-s); CP_WAITG(1); }
    else         { CP_WAITG(0); }
    __syncthreads();

    uint32_t st = sb + (uint32_t)s*ASTAGE;
    #pragma unroll
    for (int j = 0; j < 4; j++){
      uint32_t koff = (uint32_t)(j*16 + kb2)*2;
      uint32_t a0 = st + (uint32_t)(wid*16 + g4)*AROWB + koff;
      uint32_t Ah[4], Al[4];
      Ah[0] = lds32(a0);          Ah[1] = lds32(a0 + 8*AROWB);
      Ah[2] = lds32(a0 + 16);     Ah[3] = lds32(a0 + 8*AROWB + 16);
      uint32_t a1 = a0 + AQOFF;
      Al[0] = lds32(a1);          Al[1] = lds32(a1 + 8*AROWB);
      Al[2] = lds32(a1 + 16);     Al[3] = lds32(a1 + 8*AROWB + 16);
      #pragma unroll
      for (int nt = 0; nt < 8; nt++){
        uint32_t b0a = st + 2u*AQOFF + (uint32_t)(nt*8 + g4)*AROWB + koff;
        uint32_t bh[2], bl[2];
        bh[0] = lds32(b0a);         bh[1] = lds32(b0a + 16);
        bl[0] = lds32(b0a + AQOFF); bl[1] = lds32(b0a + AQOFF + 16);
        mma16816(acc[nt], Ah, bh);
        mma16816(acc[nt], Al, bh);
        mma16816(acc[nt], Ah, bl);
      }
    }
    __syncthreads();
  }

  float* pp = d_part + ((long)((b*NHEAD + h)*8 + ch))*4096;
  int r0 = wid*16 + g4;
  #pragma unroll
  for (int nt = 0; nt < 8; nt++){
    int col = nt*8 + (lane & 3)*2;
    float2 w0; w0.x = acc[nt][0]; w0.y = acc[nt][1];
    float2 w1; w1.x = acc[nt][2]; w1.y = acc[nt][3];
    *(float2*)&pp[r0*64 + col] = w0;
    *(float2*)&pp[(r0+8)*64 + col] = w1;
  }
}

// ================= xo = attn @ v, B staged from fp32 d_v =================
#define XROWB 144
#define XA_SZ (64*XROWB)
#define XB_SZ (128*XROWB)
#define X_VS (2*XA_SZ + 2*XB_SZ)       // 55296
#define XO_SMEM (X_VS + 64*528)        // + 33792 = 89088

__global__ void __launch_bounds__(128,2) xo_mma_kernel(){
  extern __shared__ char smem[];
  uint32_t sb = smem_u32(smem);
  uint32_t sAh = sb, sAl = sb + XA_SZ, sBh = sb + 2*XA_SZ, sBl = sBh + XB_SZ;
  int tid = threadIdx.x, lane = tid & 31, wid = tid >> 5;
  int ntile = blockIdx.x, h = blockIdx.y, b = blockIdx.z;
  int t0 = ntile*128;

  // stage fp32 v tile [64 e][128 t] (528B padded rows)
  {
    #pragma unroll
    for (int p = 0; p < 16; p++){
      int idx = p*128 + tid;
      int er = idx >> 5, u = idx & 31;
      CP_ASYNC16(sb + X_VS + (uint32_t)er*528 + (uint32_t)u*16,
                 d_v + ((long)b*INNER_C + h*64 + er)*NT + t0 + u*4);
    }
    CP_COMMIT();
  }
  // A: attn 64x64 fp32 -> split bf16 smem
  {
    const float* ap = d_attn + (long)(b*NHEAD+h)*4096;
    for (int i = tid; i < 4096; i += 128){
      float x = ap[i];
      __nv_bfloat16 hh, ll;
      split_bf16(x, hh, ll);
      int d = i >> 6, e = i & 63;
      *(__nv_bfloat16*)(smem + d*XROWB + e*2) = hh;
      *(__nv_bfloat16*)(smem + XA_SZ + d*XROWB + e*2) = ll;
    }
  }
  CP_WAITG(0);
  __syncthreads();

  // convert fp32 VS [e][t] -> split bf16 B [t][e]
  {
    int ep = tid >> 2, tg = tid & 3;
    const float* v0p = (const float*)(smem + X_VS + (2*ep)*528);
    const float* v1p = (const float*)(smem + X_VS + (2*ep+1)*528);
    #pragma unroll
    for (int i = 0; i < 32; i++){
      int t = tg + 4*i;
      float x0 = v0p[t], x1 = v1p[t];
      __nv_bfloat16 h0,l0,h1,l1;
      split_bf16(x0,h0,l0); split_bf16(x1,h1,l1);
      *(__nv_bfloat162*)(smem + 2*XA_SZ + t*XROWB + ep*4) = __nv_bfloat162(h0,h1);
      *(__nv_bfloat162*)(smem + 2*XA_SZ + XB_SZ + t*XROWB + ep*4) = __nv_bfloat162(l0,l1);
    }
  }
  __syncthreads();

  int g4 = lane >> 2, kb2 = (lane & 3)*2;
  float acc[4][4][4];
  #pragma unroll
  for (int i=0;i<4;i++)
    #pragma unroll
    for (int j=0;j<4;j++)
      #pragma unroll
      for (int r=0;r<4;r++) acc[i][j][r]=0.f;

  #pragma unroll
  for (int j = 0; j < 4; j++){
    uint32_t koff = (uint32_t)(j*16 + kb2)*2;
    uint32_t Ahf[4][4], Alf[4][4];
    #pragma unroll
    for (int mt = 0; mt < 4; mt++){
      uint32_t a0 = sAh + (uint32_t)(mt*16 + g4)*XROWB + koff;
      Ahf[mt][0] = lds32(a0);
      Ahf[mt][1] = lds32(a0 + 8*XROWB);
      Ahf[mt][2] = lds32(a0 + 16);
      Ahf[mt][3] = lds32(a0 + 8*XROWB + 16);
      uint32_t a1 = a0 + XA_SZ;
      Alf[mt][0] = lds32(a1);
      Alf[mt][1] = lds32(a1 + 8*XROWB);
      Alf[mt][2] = lds32(a1 + 16);
      Alf[mt][3] = lds32(a1 + 8*XROWB + 16);
    }
    #pragma unroll
    for (int nt = 0; nt < 4; nt++){
      uint32_t nr = (uint32_t)(wid*32 + nt*8 + g4);
      uint32_t b0a = sBh + nr*XROWB + koff;
      uint32_t bh[2], bl[2];
      bh[0] = lds32(b0a);         bh[1] = lds32(b0a + 16);
      bl[0] = lds32(b0a + XB_SZ); bl[1] = lds32(b0a + XB_SZ + 16);
      #pragma unroll
      for (int mt = 0; mt < 4; mt++){
        mma16816(acc[mt][nt], Ahf[mt], bh);
        mma16816(acc[mt][nt], Alf[mt], bh);
        mma16816(acc[mt][nt], Ahf[mt], bl);
      }
    }
  }

  #pragma unroll
  for (int mt = 0; mt < 4; mt++){
    int d0 = mt*16 + g4;
    #pragma unroll
    for (int nt = 0; nt < 4; nt++){
      int tt = t0 + wid*32 + nt*8 + kb2;
      long o0 = ((long)b*INNER_C + h*64 + d0)*NT + tt;
      long o1 = o0 + 8L*NT;
      __nv_bfloat16 h0,l0,h1,l1;
      split_bf16(acc[mt][nt][0], h0, l0);
      split_bf16(acc[mt][nt][1], h1, l1);
      *(__nv_bfloat162*)&d_xhi[o0] = __nv_bfloat162(h0,h1);
      *(__nv_bfloat162*)&d_xlo[o0] = __nv_bfloat162(l0,l1);
      split_bf16(acc[mt][nt][2], h0, l0);
      split_bf16(acc[mt][nt][3], h1, l1);
      *(__nv_bfloat162*)&d_xhi[o1] = __nv_bfloat162(h0,h1);
      *(__nv_bfloat162*)&d_xlo[o1] = __nv_bfloat162(l0,l1);
    }
  }
}

// ================= conversions / transposes =================
__global__ void convert_w_kernel(const float* __restrict__ W){
  int i = blockIdx.x*256 + threadIdx.x;
  __nv_bfloat16 h, l;
  split_bf16(W[i], h, l);
  d_whi[i] = h; d_wlo[i] = l;
}

__global__ void transpose_x_kernel(const float* __restrict__ x_in){
  __shared__ float tile[32][33];
  int b = blockIdx.z;
  int n0 = blockIdx.x*32, c0 = blockIdx.y*32;
  int tx = threadIdx.x, ty = threadIdx.y;
  tile[ty][tx] = x_in[((long)b*NT + n0+ty)*CD + c0+tx];
  __syncthreads();
  d_xn[((long)b*CD + c0+ty)*NT + n0+tx] = tile[tx][ty];
}

// ---------------- fused dwconv + BN: one CTA per ci plane, all 4 ocs, 2 tokens/thread ----------------
__global__ void __launch_bounds__(256) conv_qkv_kernel(
    const float* __restrict__ wq, const float* __restrict__ wk, const float* __restrict__ wv,
    const float* __restrict__ gq, const float* __restrict__ bq, const float* __restrict__ mq, const float* __restrict__ vq,
    const float* __restrict__ gk, const float* __restrict__ bk, const float* __restrict__ mk, const float* __restrict__ vk,
    const float* __restrict__ gv, const float* __restrict__ bv, const float* __restrict__ mv, const float* __restrict__ vv)
{
  int b = blockIdx.z, ci = blockIdx.y;
  int tid = threadIdx.x, lane = tid & 31, wrp = tid >> 5;
  int bx = blockIdx.x;
  int nn = (bx*256 + tid)*2;
  int hh = nn >> 7, ww = nn & 127;
  const float* xp = d_xn + ((long)b*CD + ci)*NT;

  float xv[3][4];
  #pragma unroll
  for (int dy=0; dy<3; dy++){
    int y = hh+dy-1;
    #pragma unroll
    for (int t=0; t<4; t++){
      int x = ww-1+t;
      xv[dy][t] = ((unsigned)y < 128u && (unsigned)x < 128u) ? xp[y*128+x] : 0.f;
    }
  }

  float part[8];
  #pragma unroll
  for (int j = 0; j < 4; j++){
    int oc = ci*4 + j;
    float wr0[9], wr1[9], wr2[9];
    #pragma unroll
    for (int i=0;i<9;i++){ wr0[i]=__ldg(&wq[oc*9+i]); wr1[i]=__ldg(&wk[oc*9+i]); wr2[i]=__ldg(&wv[oc*9+i]); }
    float sq0=0,sq1=0,sk0=0,sk1=0,sv0=0,sv1=0;
    #pragma unroll
    for (int dy=0; dy<3; dy++)
      #pragma unroll
      for (int t=0; t<3; t++){
        float w0=wr0[dy*3+t], w1=wr1[dy*3+t], w2=wr2[dy*3+t];
        sq0 = fmaf(xv[dy][t],   w0, sq0); sq1 = fmaf(xv[dy][t+1], w0, sq1);
        sk0 = fmaf(xv[dy][t],   w1, sk0); sk1 = fmaf(xv[dy][t+1], w1, sk1);
        sv0 = fmaf(xv[dy][t],   w2, sv0); sv1 = fmaf(xv[dy][t+1], w2, sv1);
      }
    float aq = __ldg(&gq[oc])*rsqrtf(__ldg(&vq[oc])+1e-5f), mqo = __ldg(&mq[oc]), bqo = __ldg(&bq[oc]);
    float ak = __ldg(&gk[oc])*rsqrtf(__ldg(&vk[oc])+1e-5f), mko = __ldg(&mk[oc]), bko = __ldg(&bk[oc]);
    float av = __ldg(&gv[oc])*rsqrtf(__ldg(&vv[oc])+1e-5f), mvo = __ldg(&mv[oc]), bvo = __ldg(&bv[oc]);
    float yq0 = (sq0-mqo)*aq + bqo, yq1 = (sq1-mqo)*aq + bqo;
    float yk0 = (sk0-mko)*ak + bko, yk1 = (sk1-mko)*ak + bko;
    float yv0 = (sv0-mvo)*av + bvo, yv1 = (sv1-mvo)*av + bvo;
    long o = ((long)b*INNER_C + oc)*NT + nn;
    __nv_bfloat16 h0,l0,h1,l1;
    split_bf16(yq0,h0,l0); split_bf16(yq1,h1,l1);
    *(__nv_bfloat162*)&d_qhi[o] = __nv_bfloat162(h0,h1);
    *(__nv_bfloat162*)&d_qlo[o] = __nv_bfloat162(l0,l1);
    split_bf16(yk0,h0,l0); split_bf16(yk1,h1,l1);
    *(__nv_bfloat162*)&d_khi[o] = __nv_bfloat162(h0,h1);
    *(__nv_bfloat162*)&d_klo[o] = __nv_bfloat162(l0,l1);
    float2 vv2; vv2.x = yv0; vv2.y = yv1;
    *(float2*)&d_v[o] = vv2;
    part[j]   = yq0*yq0 + yq1*yq1;
    part[4+j] = yk0*yk0 + yk1*yk1;
  }

  #pragma unroll
  for (int v = 0; v < 8; v++)
    #pragma unroll
    for (int off = 16; off > 0; off >>= 1)
      part[v] += __shfl_down_sync(0xffffffffu, part[v], off);

  __shared__ float s_red[8][8];
  if (lane == 0){
    #pragma unroll
    for (int v = 0; v < 8; v++) s_red[wrp][v] = part[v];
  }
  __syncthreads();
  if (tid < 64){
    int w = tid & 7, v = tid >> 3;
    float x = s_red[w][v];
    x += __shfl_down_sync(0xffffffffu, x, 4, 8);
    x += __shfl_down_sync(0xffffffffu, x, 2, 8);
    x += __shfl_down_sync(0xffffffffu, x, 1, 8);
    if (w == 0){
      int j = v & 3;
      long oc = (long)ci*4 + j;
      if (v < 4) d_qpart[((long)b*INNER_C + oc)*32 + bx] = x;
      else       d_kpart[((long)b*INNER_C + oc)*32 + bx] = x;
    }
  }
}

__global__ void norms_kernel(){
  int idx = blockIdx.x*256 + threadIdx.x;
  float sq=0.f, sk=0.f;
  #pragma unroll 8
  for (int c=0;c<32;c++){ sq += d_qpart[(long)idx*32+c]; sk += d_kpart[(long)idx*32+c]; }
  d_rnq[idx] = 1.f/fmaxf(sqrtf(sq),1e-12f);
  d_rnk[idx] = 1.f/fmaxf(sqrtf(sk),1e-12f);
}

__global__ void softmax_kernel(const float* __restrict__ rescale){
  int h = blockIdx.x, b = blockIdx.y;
  int d = threadIdx.x;
  float acc[64];
  #pragma unroll
  for (int e=0;e<64;e++) acc[e]=0.f;
  const float* base = d_part + ((long)(b*NHEAD+h)*8)*4096 + d*64;
  for (int ch=0; ch<8; ch++){
    const float* p = base + (long)ch*4096;
    #pragma unroll
    for (int e=0;e<64;e++) acc[e] += p[e];
  }
  float sc = rescale[h]*d_rnk[b*INNER_C + h*64 + d];
  const float* rq = &d_rnq[b*INNER_C + h*64];
  float m = -1e30f;
  #pragma unroll
  for (int e=0;e<64;e++){ acc[e] = acc[e]*sc*rq[e]; m = fmaxf(m, acc[e]); }
  float s = 0.f;
  #pragma unroll
  for (int e=0;e<64;e++){ acc[e] = expf(acc[e]-m); s += acc[e]; }
  float inv = 1.f/s;
  float* ap = d_attn + ((long)(b*NHEAD+h)*64 + d)*64;
  #pragma unroll
  for (int e=0;e<64;e++) ap[e] = acc[e]*inv;
}

// ---------------- FUSED positional convs: 16x16 token tile x 64 channels ----------------
#define P_VP_SZ (20*20*64)
#define P_G_SZ  (18*18*64)
#define POS_SMEM ((P_VP_SZ + P_G_SZ)*4)

__global__ void __launch_bounds__(256,1) conv_pos_fused_kernel(
    const float* __restrict__ w1, const float* __restrict__ w2)
{
  extern __shared__ float sm[];
  float* s_vp = sm;
  float* s_g  = sm + P_VP_SZ;
  int tid = threadIdx.x;
  int bx = blockIdx.x, c0 = blockIdx.y*64, b = blockIdx.z;
  int tx0 = (bx & 7)*16, ty0 = (bx >> 3)*16;

  #pragma unroll
  for (int i = 0; i < 25; i++){
    int idx = i*256 + tid;
    int tok = idx >> 4, c4 = (idx & 15)*4;
    int y = tok/20, x = tok - y*20;
    int gy = ty0 + y - 2, gx = tx0 + x - 2;
    float4 v = {0.f,0.f,0.f,0.f};
    if ((unsigned)gy < 128u && (unsigned)gx < 128u)
      v = *(const float4*)&d_p1[((long)b*NT + gy*128 + gx)*256 + c0 + c4];
    *(float4*)&s_vp[tok*64 + c4] = v;
  }
  __syncthreads();

  int qd = tid & 15, wk = tid >> 4;
  int cch = qd*4;
  {
    float wr[4][9];
    #pragma unroll
    for (int j=0;j<4;j++)
      #pragma unroll
      for (int i=0;i<9;i++) wr[j][i] = __ldg(&w1[(c0+cch+j)*9+i]);
    for (int t = wk; t < 324; t += 16){
      int y = t/18, x = t - y*18;
      int gy = ty0 + y - 1, gx = tx0 + x - 1;
      float4 o = {0.f,0.f,0.f,0.f};
      if ((unsigned)gy < 128u && (unsigned)gx < 128u){
        float a0=0,a1=0,a2=0,a3=0;
        #pragma unroll
        for (int dy=0; dy<3; dy++)
          #pragma unroll
          for (int dx=0; dx<3; dx++){
            float4 xv = *(const float4*)&s_vp[((y+dy)*20 + (x+dx))*64 + cch];
            int kk = dy*3+dx;
            a0 = fmaf(xv.x, wr[0][kk], a0);
            a1 = fmaf(xv.y, wr[1][kk], a1);
            a2 = fmaf(xv.z, wr[2][kk], a2);
            a3 = fmaf(xv.w, wr[3][kk], a3);
          }
        o.x = 0.5f*a0*(1.f+erff(a0*0.70710678118654752f));
        o.y = 0.5f*a1*(1.f+erff(a1*0.70710678118654752f));
        o.z = 0.5f*a2*(1.f+erff(a2*0.70710678118654752f));
        o.w = 0.5f*a3*(1.f+erff(a3*0.70710678118654752f));
      }
      *(float4*)&s_g[t*64 + cch] = o;
    }
  }
  __syncthreads();

  {
    float wr[4][9];
    #pragma unroll
    for (int j=0;j<4;j++)
      #pragma unroll
      for (int i=0;i<9;i++) wr[j][i] = __ldg(&w2[(c0+cch+j)*9+i]);
    for (int t = wk; t < 256; t += 16){
      int y = t >> 4, x = t & 15;
      float a0=0,a1=0,a2=0,a3=0;
      #pragma unroll
      for (int dy=0; dy<3; dy++)
        #pragma unroll
        for (int dx=0; dx<3; dx++){
          float4 xv = *(const float4*)&s_g[((y+dy)*18 + (x+dx))*64 + cch];
          int kk = dy*3+dx;
          a0 = fmaf(xv.x, wr[0][kk], a0);
          a1 = fmaf(xv.y, wr[1][kk], a1);
          a2 = fmaf(xv.z, wr[2][kk], a2);
          a3 = fmaf(xv.w, wr[3][kk], a3);
        }
      float4 o; o.x=a0; o.y=a1; o.z=a2; o.w=a3;
      *(float4*)&d_pe[((long)b*NT + (ty0+y)*128 + tx0+x)*256 + c0 + cch] = o;
    }
  }
}

extern "C" void kernel_launch(void* const* d_in, const int* in_sizes, int n_in,
                              void* d_out, int out_size) {
  const float* x_in  = (const float*)d_in[0];
  const float* wq    = (const float*)d_in[1];
  const float* wk    = (const float*)d_in[2];
  const float* wv    = (const float*)d_in[3];
  const float* bnq_g = (const float*)d_in[4];
  const float* bnq_b = (const float*)d_in[5];
  const float* bnq_m = (const float*)d_in[6];
  const float* bnq_v = (const float*)d_in[7];
  const float* bnk_g = (const float*)d_in[8];
  const float* bnk_b = (const float*)d_in[9];
  const float* bnk_m = (const float*)d_in[10];
  const float* bnk_v = (const float*)d_in[11];
  const float* bnv_g = (const float*)d_in[12];
  const float* bnv_b = (const float*)d_in[13];
  const float* bnv_m = (const float*)d_in[14];
  const float* bnv_v = (const float*)d_in[15];
  const float* rescale = (const float*)d_in[16];
  const float* proj_w  = (const float*)d_in[17];
  const float* proj_b  = (const float*)d_in[18];
  const float* pos_w1  = (const float*)d_in[19];
  const float* pos_w2  = (const float*)d_in[20];
  float* out = (float*)d_out;

  static int inited = 0;
  static cudaStream_t s1;
  static cudaEvent_t ev0, ev1;
  if (!inited){
    cudaFuncSetAttribute(gemm_mma_kernel, cudaFuncAttributeMaxDynamicSharedMemorySize, GEMM_SMEM);
    cudaFuncSetAttribute(gemm_v_kernel, cudaFuncAttributeMaxDynamicSharedMemorySize, GEMMV_SMEM);
    cudaFuncSetAttribute(attn_mma_kernel, cudaFuncAttributeMaxDynamicSharedMemorySize, ATTN_SMEM);
    cudaFuncSetAttribute(xo_mma_kernel, cudaFuncAttributeMaxDynamicSharedMemorySize, XO_SMEM);
    cudaFuncSetAttribute(conv_pos_fused_kernel, cudaFuncAttributeMaxDynamicSharedMemorySize, POS_SMEM);
    cudaStreamCreateWithFlags(&s1, cudaStreamNonBlocking);
    cudaEventCreateWithFlags(&ev0, cudaEventDisableTiming);
    cudaEventCreateWithFlags(&ev1, cudaEventDisableTiming);
    inited = 1;
  }

  transpose_x_kernel<<<dim3(NT/32, CD/32, NB), dim3(32,32)>>>(x_in);
  conv_qkv_kernel<<<dim3(NT/512, CD, NB), 256>>>(
      wq, wk, wv,
      bnq_g, bnq_b, bnq_m, bnq_v,
      bnk_g, bnk_b, bnk_m, bnk_v,
      bnv_g, bnv_b, bnv_m, bnv_v);
  cudaEventRecord(ev0, 0);

  // attention chain on s1 (xo needs only conv_qkv outputs + softmax)
  cudaStreamWaitEvent(s1, ev0, 0);
  norms_kernel<<<8, 256, 0, s1>>>();
  attn_mma_kernel<<<dim3(8, NHEAD, NB), 128, ATTN_SMEM, s1>>>();
  softmax_kernel<<<dim3(NHEAD, NB), 64, 0, s1>>>(rescale);
  xo_mma_kernel<<<dim3(NT/128, NHEAD, NB), 128, XO_SMEM, s1>>>();
  cudaEventRecord(ev1, s1);

  // projection chain on stream 0 (concurrent with s1)
  convert_w_kernel<<<(CD*INNER_C)/256, 256>>>(proj_w);
  gemm_v_kernel<<<dim3(2, 128, NB), 256, GEMMV_SMEM>>>(proj_b);
  conv_pos_fused_kernel<<<dim3(64, 4, NB), 256, POS_SMEM>>>(pos_w1, pos_w2);

  // final GEMM2 (needs xo [ev1] + pe [stream order])
  cudaStreamWaitEvent(0, ev1, 0);
  gemm_mma_kernel<<<dim3(2, 128, NB), 256, GEMM_SMEM>>>(proj_b, out);
}